// round 8
// baseline (speedup 1.0000x reference)
#include <cuda_runtime.h>
#include <cstdint>

#define CC 256
#define BB 1024
#define CTILE 32          // channels per block
#define RPAIRS 8          // row-pairs per block (16 rows); thread y owns pairs y and y+4
typedef unsigned long long ull;

// Scalar expanded symmetric edge weights: g_W[j*CC + c] = w3[e(min(j,c),max(j,c))], diag 0.
__device__ float g_W[CC * CC];

__global__ void build_W_kernel(const float* __restrict__ w3) {
    int idx = blockIdx.x * blockDim.x + threadIdx.x;
    if (idx >= CC * CC) return;
    int j = idx >> 8;
    int c = idx & 255;
    float v = 0.0f;
    if (j != c) {
        int p = j < c ? j : c;
        int q = j < c ? c : j;
        int e = p * (2 * CC - p - 1) / 2 + (q - p - 1);  // np.triu_indices(CC,1)
        v = w3[e];
    }
    g_W[idx] = v;
}

// ---- packed f32x2 helpers (sm_100a) ----
__device__ __forceinline__ ull pk2(float lo, float hi) {
    ull r;
    asm("mov.b64 %0, {%1, %2};" : "=l"(r) : "f"(lo), "f"(hi));
    return r;
}
__device__ __forceinline__ void upk2(ull v, float& lo, float& hi) {
    asm("mov.b64 {%0, %1}, %2;" : "=f"(lo), "=f"(hi) : "l"(v));
}
__device__ __forceinline__ ull add2(ull a, ull b) {
    ull r;
    asm("add.rn.f32x2 %0, %1, %2;" : "=l"(r) : "l"(a), "l"(b));
    return r;
}
__device__ __forceinline__ ull mul2(ull a, ull b) {
    ull r;
    asm("mul.rn.f32x2 %0, %1, %2;" : "=l"(r) : "l"(a), "l"(b));
    return r;
}
__device__ __forceinline__ ull fma2_(ull a, ull b, ull c) {
    ull r;
    asm("fma.rn.f32x2 %0, %1, %2, %3;" : "=l"(r) : "l"(a), "l"(b), "l"(c));
    return r;
}

// out[b,c] = sum_j u * (x_j - x_c) * W[j,c]
// t' = 0.505*(w2[0] + a w2[1] + a^2 w2[2] + a^3 w2[3]),  a = |x_c - x_j|
// u  = t' + (0.495/0.505)*|t'|        (== leaky_relu factor, sign folded into d)
//
// Block = (32 channels, 4 y-threads) = 128 threads; each thread owns row-pairs y and y+4
// (4 batch rows). W tile + 16 x-rows staged in smem; hot loop: 1 LDS.32 + 2 LDS.64 + 1 MOV
// feed 14 fma2 -> per-j overhead amortized over 2 packed contributions.
__global__ __launch_bounds__(128, 4) void son_main_kernel(
    const float* __restrict__ x, const float* __restrict__ w1,
    const float* __restrict__ w2, float* __restrict__ out)
{
    __shared__ float  Wt[CC][CTILE];       // 32 KB: W[j][c-tile]
    __shared__ float2 xs[RPAIRS][CC];      // 16 KB: xs[p][j] = (row 2p, row 2p+1)*w1[j]

    const int tid = threadIdx.y * CTILE + threadIdx.x;   // 0..127
    const int c0  = blockIdx.x * CTILE;
    const int r0  = blockIdx.y * (2 * RPAIRS);

    // Stage W tile: 2048 float4, 16 per thread, coalesced.
#pragma unroll
    for (int k = 0; k < 16; k++) {
        int f4idx = tid + k * 128;           // 0..2047
        int j  = f4idx >> 3;
        int qc = f4idx & 7;
        float4 v = __ldg(reinterpret_cast<const float4*>(g_W + j * CC + c0) + qc);
        *reinterpret_cast<float4*>(&Wt[j][qc * 4]) = v;
    }

    // Stage x rows: 2048 float2 entries, 16 per thread, coalesced within each row.
#pragma unroll
    for (int k = 0; k < 16; k++) {
        int idx = tid + k * 128;             // 0..2047
        int p = idx >> 8;
        int c = idx & 255;
        float w1s = w1[c];
        float lo = x[(r0 + 2 * p) * CC + c] * w1s;
        float hi = x[(r0 + 2 * p + 1) * CC + c] * w1s;
        xs[p][c] = make_float2(lo, hi);
    }
    __syncthreads();

    // prescaled polynomial coefficients (x 0.505)
    const float s0 = 0.505f * w2[0], s1 = 0.505f * w2[1];
    const float s2 = 0.505f * w2[2], s3 = 0.505f * w2[3];
    const ull C0 = pk2(s0, s0), C1 = pk2(s1, s1);
    const ull C2 = pk2(s2, s2), C3 = pk2(s3, s3);
    const float kf = 0.495f / 0.505f;
    const ull K = pk2(kf, kf);

    const int cx = threadIdx.x;              // channel lane within tile
    const int p0 = threadIdx.y;              // first row-pair
    const int p1 = threadIdx.y + 4;          // second row-pair
    const int cg = c0 + cx;                  // global channel

    const ull nxc0 = (*reinterpret_cast<const ull*>(&xs[p0][cg])) ^ 0x8000000080000000ULL;
    const ull nxc1 = (*reinterpret_cast<const ull*>(&xs[p1][cg])) ^ 0x8000000080000000ULL;

    const ull* xp0 = reinterpret_cast<const ull*>(&xs[p0][0]);
    const ull* xp1 = reinterpret_cast<const ull*>(&xs[p1][0]);

    ull acc0 = 0ULL, acc1 = 0ULL;
#pragma unroll 4
    for (int j = 0; j < CC; j++) {
        float w  = Wt[j][cx];                // LDS.32, conflict-free
        ull wpk  = pk2(w, w);                // one MOV, shared by both pairs
        ull xj0  = xp0[j];                   // LDS.64 broadcast
        ull xj1  = xp1[j];
        // pair 0
        ull d0 = add2(xj0, nxc0);
        ull a0 = d0 & 0x7fffffff7fffffffULL;
        ull t0 = fma2_(C3, a0, C2);
        t0 = fma2_(t0, a0, C1);
        t0 = fma2_(t0, a0, C0);
        ull u0 = fma2_(K, t0 & 0x7fffffff7fffffffULL, t0);
        acc0 = fma2_(u0, mul2(d0, wpk), acc0);
        // pair 1 (independent chain)
        ull d1 = add2(xj1, nxc1);
        ull a1 = d1 & 0x7fffffff7fffffffULL;
        ull t1 = fma2_(C3, a1, C2);
        t1 = fma2_(t1, a1, C1);
        t1 = fma2_(t1, a1, C0);
        ull u1 = fma2_(K, t1 & 0x7fffffff7fffffffULL, t1);
        acc1 = fma2_(u1, mul2(d1, wpk), acc1);
    }

    float lo, hi;
    upk2(acc0, lo, hi);
    out[(r0 + 2 * p0) * CC + cg]     = lo;   // coalesced: warp spans 32 consecutive c
    out[(r0 + 2 * p0 + 1) * CC + cg] = hi;
    upk2(acc1, lo, hi);
    out[(r0 + 2 * p1) * CC + cg]     = lo;
    out[(r0 + 2 * p1 + 1) * CC + cg] = hi;
}

extern "C" void kernel_launch(void* const* d_in, const int* in_sizes, int n_in,
                              void* d_out, int out_size) {
    // Identify inputs by element count (robust to ordering):
    // x: 262144, w1: 256, w2: 4, w3: 32640, diff_indices: 8355840 (unused)
    const float* x = nullptr;
    const float* w1 = nullptr;
    const float* w2 = nullptr;
    const float* w3 = nullptr;
    for (int i = 0; i < n_in; i++) {
        switch (in_sizes[i]) {
            case BB * CC:            x  = (const float*)d_in[i]; break;
            case CC:                 w1 = (const float*)d_in[i]; break;
            case 4:                  w2 = (const float*)d_in[i]; break;
            case CC * (CC - 1) / 2:  w3 = (const float*)d_in[i]; break;
            default: break;  // diff_indices not needed
        }
    }

    build_W_kernel<<<(CC * CC + 255) / 256, 256>>>(w3);
    dim3 grid(CC / CTILE, BB / (2 * RPAIRS));          // 8 x 64 = 512 blocks
    dim3 block(CTILE, 4);                               // 128 threads
    son_main_kernel<<<grid, block>>>(x, w1, w2, (float*)d_out);
}

// round 9
// speedup vs baseline: 1.1452x; 1.1452x over previous
#include <cuda_runtime.h>
#include <cstdint>

#define CC 256
#define BB 1024
typedef unsigned long long ull;

// Expanded symmetric edge weights: g_W[j*CC + c] = w3[e(min(j,c),max(j,c))], diag 0.
__device__ float g_W[CC * CC];

__global__ void build_W_kernel(const float* __restrict__ w3) {
    int idx = blockIdx.x * blockDim.x + threadIdx.x;
    if (idx >= CC * CC) return;
    int j = idx >> 8;
    int c = idx & 255;
    float v = 0.0f;
    if (j != c) {
        int p = j < c ? j : c;
        int q = j < c ? c : j;
        int e = p * (2 * CC - p - 1) / 2 + (q - p - 1);  // np.triu_indices(CC,1)
        v = w3[e];
    }
    g_W[idx] = v;
}

// Round-robin tournament over 8 channel-tiles: rounds 0..6 are perfect matchings
// (each tile exactly once per round, each unordered tile-pair exactly once overall);
// rounds 7,8 are the diagonal tiles (4 each).
__constant__ int c_I[9][4] = {
    {7,1,2,3},{7,2,3,4},{7,3,4,5},{7,4,5,6},{7,5,6,0},{7,6,0,1},{7,0,1,2},
    {0,1,2,3},{4,5,6,7}};
__constant__ int c_J[9][4] = {
    {0,6,5,4},{1,0,6,5},{2,1,0,6},{3,2,1,0},{4,3,2,1},{5,4,3,2},{6,5,4,3},
    {0,1,2,3},{4,5,6,7}};

// ---- packed f32x2 helpers (sm_100a) ----
__device__ __forceinline__ ull pk2(float lo, float hi) {
    ull r;
    asm("mov.b64 %0, {%1, %2};" : "=l"(r) : "f"(lo), "f"(hi));
    return r;
}
__device__ __forceinline__ void upk2(ull v, float& lo, float& hi) {
    asm("mov.b64 {%0, %1}, %2;" : "=f"(lo), "=f"(hi) : "l"(v));
}
__device__ __forceinline__ ull add2(ull a, ull b) {
    ull r;
    asm("add.rn.f32x2 %0, %1, %2;" : "=l"(r) : "l"(a), "l"(b));
    return r;
}
__device__ __forceinline__ ull mul2(ull a, ull b) {
    ull r;
    asm("mul.rn.f32x2 %0, %1, %2;" : "=l"(r) : "l"(a), "l"(b));
    return r;
}
__device__ __forceinline__ ull fma2_(ull a, ull b, ull c) {
    ull r;
    asm("fma.rn.f32x2 %0, %1, %2, %3;" : "=l"(r) : "l"(a), "l"(b), "l"(c));
    return r;
}
__device__ __forceinline__ void red_add(float* p, float v) {
    asm volatile("red.global.add.f32 [%0], %1;" :: "l"(p), "f"(v) : "memory");
}

// v(c,j) = u(|d|) * (x_j - x_c) * W[j,c]  is antisymmetric in (c,j); W symmetric.
// Each unordered pair is computed ONCE: row sums in accI, column sums in a
// lane-rotating accJ (negated at writeback). t' = 0.505*poly3(a), u = t' + K*|t'|.
//
// grid = (64 row-groups of 8 packed pairs, 9 rounds); block = 256 (8 warps,
// warp = one packed row-pair); each warp runs the round's 4 tile passes.
__global__ __launch_bounds__(256, 4) void son_main_kernel(
    const float* __restrict__ x, const float* __restrict__ w1,
    const float* __restrict__ w2, float* __restrict__ out)
{
    __shared__ float2 xs[8][CC];       // 16 KB: xs[p][c] = (row 2p, row 2p+1)*w1[c]
    __shared__ float  Wt[4][32 * 32];  // 16 KB: Wt[k][jy][cx] = W[Jk*32+jy][Ik*32+cx]

    const int tid  = threadIdx.x;
    const int wrp  = tid >> 5;         // row-pair within group (0..7)
    const int cx   = tid & 31;
    const int rg   = blockIdx.x;       // 0..63
    const int rnd  = blockIdx.y;       // 0..8
    const int rowb = rg * 16;

    // Stage x rows (coalesced; channel = tid)
    {
        float w1s = w1[tid];
#pragma unroll
        for (int p = 0; p < 8; p++) {
            float lo = x[(rowb + 2 * p) * CC + tid] * w1s;
            float hi = x[(rowb + 2 * p + 1) * CC + tid] * w1s;
            xs[p][tid] = make_float2(lo, hi);
        }
    }
    // Stage the round's 4 W tiles (float4, coalesced)
    {
        int jy = tid >> 3;
        int c4 = tid & 7;
#pragma unroll
        for (int k = 0; k < 4; k++) {
            int I = c_I[rnd][k], J = c_J[rnd][k];
            float4 v = __ldg(reinterpret_cast<const float4*>(
                                 g_W + (J * 32 + jy) * CC + I * 32) + c4);
            *reinterpret_cast<float4*>(&Wt[k][jy * 32 + c4 * 4]) = v;
        }
    }
    __syncthreads();

    const float s0 = 0.505f * w2[0], s1 = 0.505f * w2[1];
    const float s2 = 0.505f * w2[2], s3 = 0.505f * w2[3];
    const ull C0 = pk2(s0, s0), C1 = pk2(s1, s1);
    const ull C2 = pk2(s2, s2), C3 = pk2(s3, s3);
    const float kf = 0.495f / 0.505f;
    const ull K = pk2(kf, kf);

    const ull* xsf = reinterpret_cast<const ull*>(xs) + wrp * CC;
    const bool diag = (rnd >= 7);
    float* outr0 = out + (rowb + 2 * wrp) * CC;
    float* outr1 = outr0 + CC;

    for (int k = 0; k < 4; k++) {
        const int I = c_I[rnd][k], J = c_J[rnd][k];
        const ull nxc = xsf[I * 32 + cx] ^ 0x8000000080000000ULL;
        const ull* xJ = xsf + J * 32;
        const float* Wb = Wt[k];
        ull accI = 0ULL, accJ = 0ULL;
        float lo, hi;

        if (!diag) {
#pragma unroll
            for (int s = 0; s < 32; s++) {
                int jy  = (cx + s) & 31;
                ull xj  = xJ[jy];                  // LDS.64, rotation -> conflict-free
                float w = Wb[jy * 32 + cx];        // LDS.32, bank = cx -> conflict-free
                ull wpk = pk2(w, w);
                ull d = add2(xj, nxc);
                ull a = d & 0x7fffffff7fffffffULL;
                ull t = fma2_(C3, a, C2);
                t = fma2_(t, a, C1);
                t = fma2_(t, a, C0);
                ull u = fma2_(K, t & 0x7fffffff7fffffffULL, t);
                ull m = mul2(d, wpk);
                accI = fma2_(u, m, accI);
                accJ = fma2_(u, m, accJ);
                // rotate: lane cx hands its column partial to lane cx-1;
                // after 32 steps lane cx holds column J*32+cx's full partial.
                accJ = __shfl_sync(0xffffffffu, accJ, (cx + 1) & 31);
            }
            upk2(accI, lo, hi);
            red_add(outr0 + I * 32 + cx, lo);
            red_add(outr1 + I * 32 + cx, hi);
            ull negJ = accJ ^ 0x8000000080000000ULL;   // v(j,c) = -v(c,j)
            upk2(negJ, lo, hi);
            red_add(outr0 + J * 32 + cx, lo);
            red_add(outr1 + J * 32 + cx, hi);
        } else {
            // Diagonal tile: both directions arise naturally from row sums
            // (each lane's own row covers its side); W diag = 0 kills jy==cx.
#pragma unroll
            for (int s = 0; s < 32; s++) {
                int jy  = (cx + s) & 31;
                ull xj  = xJ[jy];
                float w = Wb[jy * 32 + cx];
                ull wpk = pk2(w, w);
                ull d = add2(xj, nxc);
                ull a = d & 0x7fffffff7fffffffULL;
                ull t = fma2_(C3, a, C2);
                t = fma2_(t, a, C1);
                t = fma2_(t, a, C0);
                ull u = fma2_(K, t & 0x7fffffff7fffffffULL, t);
                accI = fma2_(u, mul2(d, wpk), accI);
            }
            upk2(accI, lo, hi);
            red_add(outr0 + I * 32 + cx, lo);
            red_add(outr1 + I * 32 + cx, hi);
        }
    }
}

extern "C" void kernel_launch(void* const* d_in, const int* in_sizes, int n_in,
                              void* d_out, int out_size) {
    // Identify inputs by element count (robust to ordering):
    // x: 262144, w1: 256, w2: 4, w3: 32640, diff_indices: 8355840 (unused)
    const float* x = nullptr;
    const float* w1 = nullptr;
    const float* w2 = nullptr;
    const float* w3 = nullptr;
    for (int i = 0; i < n_in; i++) {
        switch (in_sizes[i]) {
            case BB * CC:            x  = (const float*)d_in[i]; break;
            case CC:                 w1 = (const float*)d_in[i]; break;
            case 4:                  w2 = (const float*)d_in[i]; break;
            case CC * (CC - 1) / 2:  w3 = (const float*)d_in[i]; break;
            default: break;  // diff_indices not needed
        }
    }

    build_W_kernel<<<(CC * CC + 255) / 256, 256>>>(w3);
    cudaMemsetAsync(d_out, 0, (size_t)out_size * sizeof(float));  // atomics accumulate into zeroed out
    dim3 grid(BB / 16, 9);     // 64 row-groups x 9 rounds = 576 blocks (one wave @ 4/SM)
    son_main_kernel<<<grid, 256>>>(x, w1, w2, (float*)d_out);
}